// round 1
// baseline (speedup 1.0000x reference)
#include <cuda_runtime.h>
#include <math.h>

static constexpr int B_ = 4, S_ = 1024, DM_ = 1024, H_ = 16, DK_ = 64, DV_ = 64;
static constexpr int LDS_ = 68;   // padded row stride (floats) for smem tiles

// Scratch (device globals: no allocation allowed)
__device__ float g_Q[B_*H_*S_*DK_];     // [b,h,s,dk]
__device__ float g_K[B_*H_*S_*DK_];
__device__ float g_V[B_*H_*S_*DV_];
__device__ float g_X[B_*S_*H_*DV_];     // attn out, concat heads: [b,s,h*dv]

// ---------------------------------------------------------------------------
// Kernel 1: fused QKV projections.
//   out[b,h,s,k] = sum_d x[b,s,d] * W[h,d,k]
// GEMM view: M = B*S = 4096 rows of x, N-tile = one head (64 cols), K = 1024.
// 64x64 tile / block, 256 threads, 4x4 micro-tile, K-chunk 16.
// ---------------------------------------------------------------------------
__global__ __launch_bounds__(256) void qkv_proj_kernel(
    const float* __restrict__ q, const float* __restrict__ k, const float* __restrict__ v,
    const float* __restrict__ Wq, const float* __restrict__ Wk, const float* __restrict__ Wv)
{
    const float* x; const float* W; float* out;
    if (blockIdx.z == 0)      { x = q; W = Wq; out = g_Q; }
    else if (blockIdx.z == 1) { x = k; W = Wk; out = g_K; }
    else                      { x = v; W = Wv; out = g_V; }

    const int m0 = blockIdx.x * 64;
    const int h  = blockIdx.y;
    const float* Wh = W + (size_t)h * DM_ * DK_;

    __shared__ float Ast[16][LDS_];   // A transposed: Ast[kk][m_local]
    __shared__ float Bs [16][64];     // Bs[kk][n_local]

    const int tid = threadIdx.x;
    const int tx = tid & 15, ty = tid >> 4;
    const int arow = tid >> 2;          // 0..63
    const int ak4  = (tid & 3) * 4;     // 0,4,8,12
    const int brow = tid >> 4;          // 0..15
    const int bc4  = (tid & 15) * 4;    // 0..60

    float acc[4][4];
    #pragma unroll
    for (int i = 0; i < 4; i++)
        #pragma unroll
        for (int j = 0; j < 4; j++) acc[i][j] = 0.f;

    for (int k0 = 0; k0 < DM_; k0 += 16) {
        float4 av = *(const float4*)&x [(size_t)(m0 + arow) * DM_ + k0 + ak4];
        float4 bv = *(const float4*)&Wh[(size_t)(k0 + brow) * DK_ + bc4];
        __syncthreads();
        Ast[ak4+0][arow] = av.x;
        Ast[ak4+1][arow] = av.y;
        Ast[ak4+2][arow] = av.z;
        Ast[ak4+3][arow] = av.w;
        *(float4*)&Bs[brow][bc4] = bv;
        __syncthreads();
        #pragma unroll
        for (int kk = 0; kk < 16; kk++) {
            float4 a = *(const float4*)&Ast[kk][ty * 4];
            float4 b = *(const float4*)&Bs [kk][tx * 4];
            float ar[4] = {a.x, a.y, a.z, a.w};
            float br[4] = {b.x, b.y, b.z, b.w};
            #pragma unroll
            for (int i = 0; i < 4; i++)
                #pragma unroll
                for (int j = 0; j < 4; j++)
                    acc[i][j] += ar[i] * br[j];
        }
    }
    #pragma unroll
    for (int i = 0; i < 4; i++) {
        const int m = m0 + ty * 4 + i;
        const int b = m >> 10, s = m & 1023;
        float4 o = make_float4(acc[i][0], acc[i][1], acc[i][2], acc[i][3]);
        *(float4*)&out[ (((size_t)b * H_ + h) * S_ + s) * DK_ + tx * 4 ] = o;
    }
}

// ---------------------------------------------------------------------------
// Kernel 2: causal flash attention, one (b,h) x 64-query tile per block.
// 256 threads; thread t owns query row r = t>>2, output columns [qd*16, qd*16+16).
// Online softmax with row-group (4 lanes) shuffles.
// ---------------------------------------------------------------------------
__global__ __launch_bounds__(256) void attn_kernel()
{
    extern __shared__ float sm[];
    float* Qs = sm;                  // 64 x LDS_
    float* Ks = sm + 64 * LDS_;
    float* Vs = sm + 2 * 64 * LDS_;
    float* Ps = sm + 3 * 64 * LDS_;

    const int qt = blockIdx.x;       // query tile 0..15
    const int bh = blockIdx.y;       // 0..63
    const int b = bh >> 4, h = bh & 15;

    const int tid = threadIdx.x;
    const int r  = tid >> 2;         // query row in tile
    const int qd = tid & 3;          // column quarter
    const int c4 = qd * 16;

    const float scale = 0.125f;      // 1/sqrt(64)
    const float* Qbase = g_Q + (size_t)bh * S_ * DK_ + (size_t)qt * 64 * DK_;
    const float* Kbase = g_K + (size_t)bh * S_ * DK_;
    const float* Vbase = g_V + (size_t)bh * S_ * DK_;

    // load Q tile (scaled)
    #pragma unroll
    for (int t = 0; t < 4; t++) {
        int lin = tid + t * 256;               // float4 index 0..1023
        int row = lin >> 4, cc = (lin & 15) * 4;
        float4 vq = *(const float4*)&Qbase[row * DK_ + cc];
        vq.x *= scale; vq.y *= scale; vq.z *= scale; vq.w *= scale;
        *(float4*)&Qs[row * LDS_ + cc] = vq;
    }

    float acc[16];
    #pragma unroll
    for (int i = 0; i < 16; i++) acc[i] = 0.f;
    float m_i = -1e30f, l_i = 0.f;

    for (int j = 0; j <= qt; j++) {
        const float* Kt = Kbase + (size_t)j * 64 * DK_;
        const float* Vt = Vbase + (size_t)j * 64 * DK_;
        __syncthreads();   // previous iteration fully consumed Ks/Vs/Ps
        #pragma unroll
        for (int t = 0; t < 4; t++) {
            int lin = tid + t * 256;
            int row = lin >> 4, cc = (lin & 15) * 4;
            *(float4*)&Ks[row * LDS_ + cc] = *(const float4*)&Kt[row * DK_ + cc];
            *(float4*)&Vs[row * LDS_ + cc] = *(const float4*)&Vt[row * DK_ + cc];
        }
        __syncthreads();

        // scores: keys c4..c4+15 against my query row
        float s[16];
        #pragma unroll
        for (int i = 0; i < 16; i++) s[i] = 0.f;
        #pragma unroll
        for (int d = 0; d < DK_; d += 4) {
            float4 qv = *(const float4*)&Qs[r * LDS_ + d];
            #pragma unroll
            for (int kc = 0; kc < 16; kc++) {
                float4 kv = *(const float4*)&Ks[(c4 + kc) * LDS_ + d];
                s[kc] += qv.x * kv.x + qv.y * kv.y + qv.z * kv.z + qv.w * kv.w;
            }
        }
        if (j == qt) {
            #pragma unroll
            for (int kc = 0; kc < 16; kc++)
                if (c4 + kc > r) s[kc] = -1e30f;
        }

        // online softmax (row spans 4 consecutive lanes)
        float mloc = s[0];
        #pragma unroll
        for (int i = 1; i < 16; i++) mloc = fmaxf(mloc, s[i]);
        mloc = fmaxf(mloc, __shfl_xor_sync(0xffffffffu, mloc, 1));
        mloc = fmaxf(mloc, __shfl_xor_sync(0xffffffffu, mloc, 2));
        const float mnew = fmaxf(m_i, mloc);
        const float fac = __expf(m_i - mnew);
        float lsum = 0.f;
        #pragma unroll
        for (int kc = 0; kc < 16; kc++) {
            float p = __expf(s[kc] - mnew);
            s[kc] = p;
            lsum += p;
        }
        lsum += __shfl_xor_sync(0xffffffffu, lsum, 1);
        lsum += __shfl_xor_sync(0xffffffffu, lsum, 2);
        l_i = l_i * fac + lsum;
        m_i = mnew;
        #pragma unroll
        for (int i = 0; i < 16; i++) acc[i] *= fac;

        #pragma unroll
        for (int kc = 0; kc < 16; kc += 4)
            *(float4*)&Ps[r * LDS_ + c4 + kc] =
                make_float4(s[kc], s[kc+1], s[kc+2], s[kc+3]);
        __syncthreads();

        // O += P @ V
        #pragma unroll 8
        for (int kk = 0; kk < 64; kk++) {
            const float p = Ps[r * LDS_ + kk];
            #pragma unroll
            for (int cc = 0; cc < 16; cc += 4) {
                float4 vv = *(const float4*)&Vs[kk * LDS_ + c4 + cc];
                acc[cc]     += p * vv.x;
                acc[cc + 1] += p * vv.y;
                acc[cc + 2] += p * vv.z;
                acc[cc + 3] += p * vv.w;
            }
        }
    }

    const float rl = 1.f / l_i;
    const int srow = qt * 64 + r;
    float* outp = g_X + ((size_t)b * S_ + srow) * (H_ * DV_) + h * DV_ + c4;
    #pragma unroll
    for (int cc = 0; cc < 16; cc += 4)
        *(float4*)&outp[cc] = make_float4(acc[cc] * rl, acc[cc+1] * rl,
                                          acc[cc+2] * rl, acc[cc+3] * rl);
}

// ---------------------------------------------------------------------------
// Kernel 3: output projection  y[m,d] = sum_e X[m,e] * Wo[d,e]
// Both operands are K-contiguous; load both transposed into smem.
// ---------------------------------------------------------------------------
__global__ __launch_bounds__(256) void out_proj_kernel(
    const float* __restrict__ Wo, float* __restrict__ y)
{
    const int m0 = blockIdx.x * 64;
    const int n0 = blockIdx.y * 64;

    __shared__ float Ast[16][LDS_];   // Ast[kk][m_local]
    __shared__ float Bst[16][LDS_];   // Bst[kk][n_local]

    const int tid = threadIdx.x;
    const int tx = tid & 15, ty = tid >> 4;
    const int arow = tid >> 2;           // 0..63
    const int ak4  = (tid & 3) * 4;

    float acc[4][4];
    #pragma unroll
    for (int i = 0; i < 4; i++)
        #pragma unroll
        for (int j = 0; j < 4; j++) acc[i][j] = 0.f;

    for (int k0 = 0; k0 < DM_; k0 += 16) {
        float4 av = *(const float4*)&g_X[(size_t)(m0 + arow) * DM_ + k0 + ak4];
        float4 bv = *(const float4*)&Wo [(size_t)(n0 + arow) * DM_ + k0 + ak4];
        __syncthreads();
        Ast[ak4+0][arow] = av.x;  Bst[ak4+0][arow] = bv.x;
        Ast[ak4+1][arow] = av.y;  Bst[ak4+1][arow] = bv.y;
        Ast[ak4+2][arow] = av.z;  Bst[ak4+2][arow] = bv.z;
        Ast[ak4+3][arow] = av.w;  Bst[ak4+3][arow] = bv.w;
        __syncthreads();
        #pragma unroll
        for (int kk = 0; kk < 16; kk++) {
            float4 a = *(const float4*)&Ast[kk][ty * 4];
            float4 b = *(const float4*)&Bst[kk][tx * 4];
            float ar[4] = {a.x, a.y, a.z, a.w};
            float br[4] = {b.x, b.y, b.z, b.w};
            #pragma unroll
            for (int i = 0; i < 4; i++)
                #pragma unroll
                for (int j = 0; j < 4; j++)
                    acc[i][j] += ar[i] * br[j];
        }
    }
    #pragma unroll
    for (int i = 0; i < 4; i++) {
        const int m = m0 + ty * 4 + i;
        float4 o = make_float4(acc[i][0], acc[i][1], acc[i][2], acc[i][3]);
        *(float4*)&y[(size_t)m * DM_ + n0 + tx * 4] = o;
    }
}

// ---------------------------------------------------------------------------
extern "C" void kernel_launch(void* const* d_in, const int* in_sizes, int n_in,
                              void* d_out, int out_size)
{
    const float* q  = (const float*)d_in[0];
    const float* k  = (const float*)d_in[1];
    const float* v  = (const float*)d_in[2];
    const float* Wq = (const float*)d_in[3];
    const float* Wk = (const float*)d_in[4];
    const float* Wv = (const float*)d_in[5];
    const float* Wo = (const float*)d_in[6];
    float* y = (float*)d_out;

    const int attn_smem = 4 * 64 * LDS_ * (int)sizeof(float);  // 69632 B
    cudaFuncSetAttribute(attn_kernel, cudaFuncAttributeMaxDynamicSharedMemorySize, attn_smem);

    qkv_proj_kernel<<<dim3(S_ * B_ / 64, H_, 3), 256>>>(q, k, v, Wq, Wk, Wv);
    attn_kernel<<<dim3(S_ / 64, B_ * H_), 256, attn_smem>>>();
    out_proj_kernel<<<dim3(S_ * B_ / 64, DM_ / 64), 256>>>(Wo, y);
}

// round 2
// speedup vs baseline: 6.3763x; 6.3763x over previous
#include <cuda_runtime.h>
#include <math.h>
#include <stdint.h>

static constexpr int B_ = 4, S_ = 1024, DM_ = 1024, H_ = 16, DK_ = 64, DV_ = 64;

// Scratch (device globals: no allocation allowed)
__device__ float g_Q[B_*H_*S_*DK_];     // [b,h,s,dk]
__device__ float g_K[B_*H_*S_*DK_];
__device__ float g_V[B_*H_*S_*DV_];
__device__ float g_X[B_*S_*H_*DV_];     // attn out, concat heads: [b,s,h*dv]

__device__ __forceinline__ uint32_t f2tf(float x) {
    uint32_t r;
    asm("cvt.rna.tf32.f32 %0, %1;" : "=r"(r) : "f"(x));
    return r;
}

// D += A * B  (m16n8k8, tf32 inputs, f32 accumulate)
__device__ __forceinline__ void mma8(float* c, const uint32_t* a, const uint32_t* b) {
    asm volatile(
        "mma.sync.aligned.m16n8k8.row.col.f32.tf32.tf32.f32 "
        "{%0,%1,%2,%3}, {%4,%5,%6,%7}, {%8,%9}, {%0,%1,%2,%3};"
        : "+f"(c[0]), "+f"(c[1]), "+f"(c[2]), "+f"(c[3])
        : "r"(a[0]), "r"(a[1]), "r"(a[2]), "r"(a[3]), "r"(b[0]), "r"(b[1]));
}

// ---------------------------------------------------------------------------
// Kernel 1: fused QKV projections with tf32 mma.
//   out[b,h,s,k] = sum_d x[b,s,d] * W[h,d,k]
// Block: 128(M) x 64(N) tile, 256 threads = 8 warps (4m x 2n), warp tile 32x32.
// ---------------------------------------------------------------------------
__global__ __launch_bounds__(256) void qkv_proj_mma(
    const float* __restrict__ q, const float* __restrict__ k, const float* __restrict__ v,
    const float* __restrict__ Wq, const float* __restrict__ Wk, const float* __restrict__ Wv)
{
    const float* x; const float* W; float* out;
    if (blockIdx.z == 0)      { x = q; W = Wq; out = g_Q; }
    else if (blockIdx.z == 1) { x = k; W = Wk; out = g_K; }
    else                      { x = v; W = Wv; out = g_V; }

    const int m0 = blockIdx.x * 128;
    const int h  = blockIdx.y;
    const float* Wh = W + (size_t)h * DM_ * DK_;

    __shared__ uint32_t As[128][36];   // [m][k-in-chunk], stride 36 -> frag banks (4g+tig)
    __shared__ uint32_t Bs[32][72];    // [k][n], stride 72 -> frag banks (8tig+g)

    const int tid = threadIdx.x, lane = tid & 31, warp = tid >> 5;
    const int wm = warp & 3, wn = warp >> 2;
    const int g = lane >> 2, tig = lane & 3;

    float acc[2][4][4];
    #pragma unroll
    for (int mt = 0; mt < 2; mt++)
        #pragma unroll
        for (int nt = 0; nt < 4; nt++)
            #pragma unroll
            for (int i = 0; i < 4; i++) acc[mt][nt][i] = 0.f;

    for (int k0 = 0; k0 < DM_; k0 += 32) {
        float4 a4[4], b4[2];
        #pragma unroll
        for (int t = 0; t < 4; t++) {
            int idx = tid + t * 256, r = idx >> 3, c = (idx & 7) * 4;
            a4[t] = *(const float4*)&x[(size_t)(m0 + r) * DM_ + k0 + c];
        }
        #pragma unroll
        for (int t = 0; t < 2; t++) {
            int idx = tid + t * 256, r = idx >> 4, c = (idx & 15) * 4;
            b4[t] = *(const float4*)&Wh[(size_t)(k0 + r) * DK_ + c];
        }
        __syncthreads();
        #pragma unroll
        for (int t = 0; t < 4; t++) {
            int idx = tid + t * 256, r = idx >> 3, c = (idx & 7) * 4;
            As[r][c] = f2tf(a4[t].x); As[r][c+1] = f2tf(a4[t].y);
            As[r][c+2] = f2tf(a4[t].z); As[r][c+3] = f2tf(a4[t].w);
        }
        #pragma unroll
        for (int t = 0; t < 2; t++) {
            int idx = tid + t * 256, r = idx >> 4, c = (idx & 15) * 4;
            Bs[r][c] = f2tf(b4[t].x); Bs[r][c+1] = f2tf(b4[t].y);
            Bs[r][c+2] = f2tf(b4[t].z); Bs[r][c+3] = f2tf(b4[t].w);
        }
        __syncthreads();
        #pragma unroll
        for (int ks = 0; ks < 4; ks++) {
            uint32_t af[2][4];
            #pragma unroll
            for (int mt = 0; mt < 2; mt++) {
                int rr = wm * 32 + mt * 16 + g;
                af[mt][0] = As[rr][ks*8 + tig];
                af[mt][1] = As[rr + 8][ks*8 + tig];
                af[mt][2] = As[rr][ks*8 + tig + 4];
                af[mt][3] = As[rr + 8][ks*8 + tig + 4];
            }
            #pragma unroll
            for (int nt = 0; nt < 4; nt++) {
                uint32_t bf[2];
                int cc = wn * 32 + nt * 8 + g;
                bf[0] = Bs[ks*8 + tig][cc];
                bf[1] = Bs[ks*8 + tig + 4][cc];
                mma8(acc[0][nt], af[0], bf);
                mma8(acc[1][nt], af[1], bf);
            }
        }
    }
    #pragma unroll
    for (int mt = 0; mt < 2; mt++) {
        #pragma unroll
        for (int half = 0; half < 2; half++) {
            int m = m0 + wm * 32 + mt * 16 + g + half * 8;
            int b = m >> 10, s = m & 1023;
            float* op = &out[(((size_t)b * H_ + h) * S_ + s) * DK_];
            #pragma unroll
            for (int nt = 0; nt < 4; nt++) {
                int nn = wn * 32 + nt * 8 + 2 * tig;
                float2 val = half ? make_float2(acc[mt][nt][2], acc[mt][nt][3])
                                  : make_float2(acc[mt][nt][0], acc[mt][nt][1]);
                *(float2*)&op[nn] = val;
            }
        }
    }
}

// ---------------------------------------------------------------------------
// Kernel 2: causal flash attention with tf32 mma.
// Block = (bh, 64-query tile), 128 threads = 4 warps; warp owns 16 query rows.
// ---------------------------------------------------------------------------
__global__ __launch_bounds__(128) void attn_mma()
{
    extern __shared__ uint32_t smU[];
    uint32_t (*Qs)[68] = (uint32_t(*)[68])smU;                       // Q (scaled, tf32)
    uint32_t (*Ks)[68] = (uint32_t(*)[68])(smU + 64*68);             // K [key][d]
    uint32_t (*Vs)[72] = (uint32_t(*)[72])(smU + 2*64*68);           // V [key][dv]
    uint32_t (*Ps)[68] = (uint32_t(*)[68])(smU + 2*64*68 + 64*72);   // P [qrow][key]

    const int qt = blockIdx.x, bh = blockIdx.y;
    const int b = bh >> 4, h = bh & 15;
    const int tid = threadIdx.x, lane = tid & 31, warp = tid >> 5;
    const int g = lane >> 2, tig = lane & 3;

    const float* Qg = g_Q + (size_t)bh * S_ * DK_ + (size_t)qt * 64 * DK_;
    const float* Kg = g_K + (size_t)bh * S_ * DK_;
    const float* Vg = g_V + (size_t)bh * S_ * DK_;

    // stage Q tile (pre-scaled by 1/sqrt(dk), converted to tf32)
    #pragma unroll
    for (int t = 0; t < 8; t++) {
        int idx = tid + t * 128, r = idx >> 4, c = (idx & 15) * 4;
        float4 qv = *(const float4*)&Qg[r * DK_ + c];
        Qs[r][c]   = f2tf(qv.x * 0.125f); Qs[r][c+1] = f2tf(qv.y * 0.125f);
        Qs[r][c+2] = f2tf(qv.z * 0.125f); Qs[r][c+3] = f2tf(qv.w * 0.125f);
    }

    float O[8][4];
    #pragma unroll
    for (int nt = 0; nt < 8; nt++)
        #pragma unroll
        for (int i = 0; i < 4; i++) O[nt][i] = 0.f;
    float m0r = -1e30f, m1r = -1e30f, l0 = 0.f, l1 = 0.f;

    for (int j = 0; j <= qt; j++) {
        const float* Kt = Kg + (size_t)j * 64 * DK_;
        const float* Vt = Vg + (size_t)j * 64 * DK_;
        __syncthreads();   // previous iteration fully consumed Ks/Vs (and j==0: Qs staged)
        #pragma unroll
        for (int t = 0; t < 8; t++) {
            int idx = tid + t * 128, r = idx >> 4, c = (idx & 15) * 4;
            float4 kv = *(const float4*)&Kt[r * DK_ + c];
            float4 vv = *(const float4*)&Vt[r * DK_ + c];
            Ks[r][c]   = f2tf(kv.x); Ks[r][c+1] = f2tf(kv.y);
            Ks[r][c+2] = f2tf(kv.z); Ks[r][c+3] = f2tf(kv.w);
            Vs[r][c]   = f2tf(vv.x); Vs[r][c+1] = f2tf(vv.y);
            Vs[r][c+2] = f2tf(vv.z); Vs[r][c+3] = f2tf(vv.w);
        }
        __syncthreads();

        // ---- scores S = Q K^T (16 rows x 64 keys per warp) ----
        float Sf[8][4];
        #pragma unroll
        for (int nt = 0; nt < 8; nt++)
            #pragma unroll
            for (int i = 0; i < 4; i++) Sf[nt][i] = 0.f;

        #pragma unroll
        for (int ks = 0; ks < 8; ks++) {
            uint32_t af[4];
            int rr = warp * 16 + g;
            af[0] = Qs[rr][ks*8 + tig];
            af[1] = Qs[rr + 8][ks*8 + tig];
            af[2] = Qs[rr][ks*8 + tig + 4];
            af[3] = Qs[rr + 8][ks*8 + tig + 4];
            #pragma unroll
            for (int nt = 0; nt < 8; nt++) {
                uint32_t bf[2];
                bf[0] = Ks[nt*8 + g][ks*8 + tig];
                bf[1] = Ks[nt*8 + g][ks*8 + tig + 4];
                mma8(Sf[nt], af, bf);
            }
        }

        // ---- causal mask (diagonal tile only) ----
        if (j == qt) {
            int row0 = warp * 16 + g, row1 = row0 + 8;
            #pragma unroll
            for (int nt = 0; nt < 8; nt++) {
                int c0 = nt * 8 + 2 * tig, c1 = c0 + 1;
                if (c0 > row0) Sf[nt][0] = -1e30f;
                if (c1 > row0) Sf[nt][1] = -1e30f;
                if (c0 > row1) Sf[nt][2] = -1e30f;
                if (c1 > row1) Sf[nt][3] = -1e30f;
            }
        }

        // ---- online softmax ----
        float mx0 = -1e30f, mx1 = -1e30f;
        #pragma unroll
        for (int nt = 0; nt < 8; nt++) {
            mx0 = fmaxf(mx0, fmaxf(Sf[nt][0], Sf[nt][1]));
            mx1 = fmaxf(mx1, fmaxf(Sf[nt][2], Sf[nt][3]));
        }
        mx0 = fmaxf(mx0, __shfl_xor_sync(0xffffffffu, mx0, 1));
        mx0 = fmaxf(mx0, __shfl_xor_sync(0xffffffffu, mx0, 2));
        mx1 = fmaxf(mx1, __shfl_xor_sync(0xffffffffu, mx1, 1));
        mx1 = fmaxf(mx1, __shfl_xor_sync(0xffffffffu, mx1, 2));
        const float mn0 = fmaxf(m0r, mx0), mn1 = fmaxf(m1r, mx1);
        const float f0 = __expf(m0r - mn0), f1 = __expf(m1r - mn1);
        float s0 = 0.f, s1 = 0.f;
        {
            int rr = warp * 16 + g;
            #pragma unroll
            for (int nt = 0; nt < 8; nt++) {
                float p0 = __expf(Sf[nt][0] - mn0), p1 = __expf(Sf[nt][1] - mn0);
                float p2 = __expf(Sf[nt][2] - mn1), p3 = __expf(Sf[nt][3] - mn1);
                s0 += p0 + p1; s1 += p2 + p3;
                int cc = nt * 8 + 2 * tig;
                Ps[rr][cc] = f2tf(p0);     Ps[rr][cc+1] = f2tf(p1);
                Ps[rr + 8][cc] = f2tf(p2); Ps[rr + 8][cc+1] = f2tf(p3);
                O[nt][0] *= f0; O[nt][1] *= f0;
                O[nt][2] *= f1; O[nt][3] *= f1;
            }
        }
        s0 += __shfl_xor_sync(0xffffffffu, s0, 1);
        s0 += __shfl_xor_sync(0xffffffffu, s0, 2);
        s1 += __shfl_xor_sync(0xffffffffu, s1, 1);
        s1 += __shfl_xor_sync(0xffffffffu, s1, 2);
        l0 = l0 * f0 + s0; l1 = l1 * f1 + s1;
        m0r = mn0; m1r = mn1;
        __syncwarp();   // each warp consumes only its own P rows

        // ---- O += P V ----
        #pragma unroll
        for (int kt = 0; kt < 8; kt++) {
            uint32_t af[4];
            int rr = warp * 16 + g;
            af[0] = Ps[rr][kt*8 + tig];
            af[1] = Ps[rr + 8][kt*8 + tig];
            af[2] = Ps[rr][kt*8 + tig + 4];
            af[3] = Ps[rr + 8][kt*8 + tig + 4];
            #pragma unroll
            for (int nt = 0; nt < 8; nt++) {
                uint32_t bf[2];
                bf[0] = Vs[kt*8 + tig][nt*8 + g];
                bf[1] = Vs[kt*8 + tig + 4][nt*8 + g];
                mma8(O[nt], af, bf);
            }
        }
    }

    const float rl0 = 1.f / l0, rl1 = 1.f / l1;
    const int row0 = qt * 64 + warp * 16 + g;
    float* xp0 = g_X + ((size_t)b * S_ + row0) * (H_ * DV_) + h * DV_;
    float* xp1 = xp0 + (size_t)8 * (H_ * DV_);
    #pragma unroll
    for (int nt = 0; nt < 8; nt++) {
        int cc = nt * 8 + 2 * tig;
        *(float2*)&xp0[cc] = make_float2(O[nt][0] * rl0, O[nt][1] * rl0);
        *(float2*)&xp1[cc] = make_float2(O[nt][2] * rl1, O[nt][3] * rl1);
    }
}

// ---------------------------------------------------------------------------
// Kernel 3: output projection  y[m,d] = sum_e X[m,e] * Wo[d,e]  (tf32 mma)
// ---------------------------------------------------------------------------
__global__ __launch_bounds__(256) void out_proj_mma(
    const float* __restrict__ Wo, float* __restrict__ y)
{
    const int m0 = blockIdx.x * 128;
    const int n0 = blockIdx.y * 64;

    __shared__ uint32_t As[128][36];   // X rows, [m][k]
    __shared__ uint32_t Bs[64][36];    // Wo rows, [n][k]

    const int tid = threadIdx.x, lane = tid & 31, warp = tid >> 5;
    const int wm = warp & 3, wn = warp >> 2;
    const int g = lane >> 2, tig = lane & 3;

    float acc[2][4][4];
    #pragma unroll
    for (int mt = 0; mt < 2; mt++)
        #pragma unroll
        for (int nt = 0; nt < 4; nt++)
            #pragma unroll
            for (int i = 0; i < 4; i++) acc[mt][nt][i] = 0.f;

    for (int k0 = 0; k0 < DM_; k0 += 32) {
        float4 a4[4], b4[2];
        #pragma unroll
        for (int t = 0; t < 4; t++) {
            int idx = tid + t * 256, r = idx >> 3, c = (idx & 7) * 4;
            a4[t] = *(const float4*)&g_X[(size_t)(m0 + r) * DM_ + k0 + c];
        }
        #pragma unroll
        for (int t = 0; t < 2; t++) {
            int idx = tid + t * 256, r = idx >> 3, c = (idx & 7) * 4;
            b4[t] = *(const float4*)&Wo[(size_t)(n0 + r) * DM_ + k0 + c];
        }
        __syncthreads();
        #pragma unroll
        for (int t = 0; t < 4; t++) {
            int idx = tid + t * 256, r = idx >> 3, c = (idx & 7) * 4;
            As[r][c] = f2tf(a4[t].x); As[r][c+1] = f2tf(a4[t].y);
            As[r][c+2] = f2tf(a4[t].z); As[r][c+3] = f2tf(a4[t].w);
        }
        #pragma unroll
        for (int t = 0; t < 2; t++) {
            int idx = tid + t * 256, r = idx >> 3, c = (idx & 7) * 4;
            Bs[r][c] = f2tf(b4[t].x); Bs[r][c+1] = f2tf(b4[t].y);
            Bs[r][c+2] = f2tf(b4[t].z); Bs[r][c+3] = f2tf(b4[t].w);
        }
        __syncthreads();
        #pragma unroll
        for (int ks = 0; ks < 4; ks++) {
            uint32_t af[2][4];
            #pragma unroll
            for (int mt = 0; mt < 2; mt++) {
                int rr = wm * 32 + mt * 16 + g;
                af[mt][0] = As[rr][ks*8 + tig];
                af[mt][1] = As[rr + 8][ks*8 + tig];
                af[mt][2] = As[rr][ks*8 + tig + 4];
                af[mt][3] = As[rr + 8][ks*8 + tig + 4];
            }
            #pragma unroll
            for (int nt = 0; nt < 4; nt++) {
                uint32_t bf[2];
                int cc = wn * 32 + nt * 8 + g;
                bf[0] = Bs[cc][ks*8 + tig];
                bf[1] = Bs[cc][ks*8 + tig + 4];
                mma8(acc[0][nt], af[0], bf);
                mma8(acc[1][nt], af[1], bf);
            }
        }
    }
    #pragma unroll
    for (int mt = 0; mt < 2; mt++) {
        #pragma unroll
        for (int half = 0; half < 2; half++) {
            int m = m0 + wm * 32 + mt * 16 + g + half * 8;
            #pragma unroll
            for (int nt = 0; nt < 4; nt++) {
                int nn = wn * 32 + nt * 8 + 2 * tig;
                float2 val = half ? make_float2(acc[mt][nt][2], acc[mt][nt][3])
                                  : make_float2(acc[mt][nt][0], acc[mt][nt][1]);
                *(float2*)&y[(size_t)m * DM_ + n0 + nn] = val;
            }
        }
    }
}

// ---------------------------------------------------------------------------
extern "C" void kernel_launch(void* const* d_in, const int* in_sizes, int n_in,
                              void* d_out, int out_size)
{
    const float* q  = (const float*)d_in[0];
    const float* k  = (const float*)d_in[1];
    const float* v  = (const float*)d_in[2];
    const float* Wq = (const float*)d_in[3];
    const float* Wk = (const float*)d_in[4];
    const float* Wv = (const float*)d_in[5];
    const float* Wo = (const float*)d_in[6];
    float* y = (float*)d_out;

    const int attn_smem = (3 * 64 * 68 + 64 * 72) * (int)sizeof(uint32_t);  // 70656 B
    cudaFuncSetAttribute(attn_mma, cudaFuncAttributeMaxDynamicSharedMemorySize, attn_smem);

    qkv_proj_mma<<<dim3(S_ * B_ / 128, H_, 3), 256>>>(q, k, v, Wq, Wk, Wv);
    attn_mma<<<dim3(S_ / 64, B_ * H_), 128, attn_smem>>>();
    out_proj_mma<<<dim3(S_ * B_ / 128, DM_ / 64), 256>>>(Wo, y);
}